// round 2
// baseline (speedup 1.0000x reference)
#include <cuda_runtime.h>
#include <cuda_bf16.h>
#include <math.h>

// ---------------------------------------------------------------------------
// SketchWalkLlamaAttention  (B=1, S=4096, HID=2048, NH=16, NKV=4, D=128,
//                            BLK=64, M=32, K_TOP=8, nblk=64)
// Full fp32 pipeline:
//   1. q/k/v = hs @ Wq/Wk/Wv          (SGEMM)
//   2. RoPE on q,k
//   3. Sq/Sk block sketches (mean-of-rows @ H_sketch)
//   4. block scores + causal mask + diag boost + top-8
//   5. sparse block attention (64 q x 8*64 k per (head, qblock))
//   6. out = attn @ Wo                 (SGEMM)
// ---------------------------------------------------------------------------

#define S_LEN 4096
#define HID   2048
#define NH    16
#define NKV   4
#define DH    128
#define BLK   64
#define NBLK  64
#define MSK   32
#define KTOP  8
#define NEGV  (-1e9f)

// scratch (device globals: no allocation allowed)
__device__ float g_q[S_LEN * NH * DH];     // 32 MB
__device__ float g_k[S_LEN * NKV * DH];    // 8 MB
__device__ float g_v[S_LEN * NKV * DH];    // 8 MB
__device__ float g_attn[S_LEN * NH * DH];  // 32 MB
__device__ float g_Sq[NH * NBLK * MSK];
__device__ float g_Sk[NKV * NBLK * MSK];
__device__ int   g_idx[NH * NBLK * KTOP];

// ---------------------------------------------------------------------------
// SGEMM: C[M,N] = A[M,K] @ B[K,N], all row-major, M%128==0, N%128==0, K%8==0
// 128x128 tile, BK=8, 256 threads, 8x8 per thread.
// ---------------------------------------------------------------------------
__global__ __launch_bounds__(256, 1)
void sgemm128(const float* __restrict__ A, const float* __restrict__ B,
              float* __restrict__ C, int M, int N, int K)
{
    __shared__ float As[8][128];
    __shared__ float Bs[8][128];
    const int tid = threadIdx.x;
    const int tx = tid & 15;
    const int ty = tid >> 4;
    const int row0 = blockIdx.y * 128;
    const int col0 = blockIdx.x * 128;

    float acc[8][8];
#pragma unroll
    for (int i = 0; i < 8; i++)
#pragma unroll
        for (int j = 0; j < 8; j++) acc[i][j] = 0.f;

    const int a_row = tid >> 1;
    const int a_col = (tid & 1) * 4;
    const int b_row = tid >> 5;
    const int b_col = (tid & 31) * 4;

    const float* Aptr = A + (size_t)(row0 + a_row) * K + a_col;
    const float* Bptr = B + (size_t)b_row * N + col0 + b_col;

    for (int k0 = 0; k0 < K; k0 += 8) {
        float4 av = *(const float4*)(Aptr + k0);
        float4 bv = *(const float4*)(Bptr + (size_t)k0 * N);
        As[a_col + 0][a_row] = av.x;
        As[a_col + 1][a_row] = av.y;
        As[a_col + 2][a_row] = av.z;
        As[a_col + 3][a_row] = av.w;
        *(float4*)&Bs[b_row][b_col] = bv;
        __syncthreads();
#pragma unroll
        for (int k = 0; k < 8; k++) {
            float ar[8], br[8];
#pragma unroll
            for (int i = 0; i < 4; i++) {
                ar[i]     = As[k][ty * 4 + i];
                ar[4 + i] = As[k][64 + ty * 4 + i];
            }
#pragma unroll
            for (int j = 0; j < 4; j++) {
                br[j]     = Bs[k][tx * 4 + j];
                br[4 + j] = Bs[k][64 + tx * 4 + j];
            }
#pragma unroll
            for (int i = 0; i < 8; i++)
#pragma unroll
                for (int j = 0; j < 8; j++) acc[i][j] = fmaf(ar[i], br[j], acc[i][j]);
        }
        __syncthreads();
    }

#pragma unroll
    for (int i = 0; i < 8; i++) {
        int r = (i < 4) ? (ty * 4 + i) : (64 + ty * 4 + (i - 4));
        float* Crow = C + (size_t)(row0 + r) * N + col0;
        float4 v0 = make_float4(acc[i][0], acc[i][1], acc[i][2], acc[i][3]);
        float4 v1 = make_float4(acc[i][4], acc[i][5], acc[i][6], acc[i][7]);
        *(float4*)(Crow + tx * 4) = v0;
        *(float4*)(Crow + 64 + tx * 4) = v1;
    }
}

// ---------------------------------------------------------------------------
// RoPE in place: x is (S, H, 128). H = NH for q, NKV for k.
// q'[d] = q[d]*cos - q[d+64]*sin ; q'[d+64] = q[d+64]*cos + q[d]*sin (d<64)
// ---------------------------------------------------------------------------
__global__ void rope_kernel(float* __restrict__ x, const int* __restrict__ pos, int H)
{
    int i = blockIdx.x * blockDim.x + threadIdx.x;
    int total = S_LEN * H * 64;
    if (i >= total) return;
    int half = i & 63;
    int sh = i >> 6;
    int s = sh / H;
    float p = (float)pos[s];
    // inv_freq = 10000^(-half/64); compute in double then round, matches f32 ref
    float inv = (float)exp(-(double)half * 0.14391156831212787); // ln(1e4)/64
    float ang = p * inv;
    float sn, cs;
    sincosf(ang, &sn, &cs);
    float* base = x + (size_t)sh * DH;
    float x1 = base[half];
    float x2 = base[half + 64];
    base[half]      = x1 * cs - x2 * sn;
    base[half + 64] = x2 * cs + x1 * sn;
}

// ---------------------------------------------------------------------------
// Sketch: Sout[h][blk][m] = mean_{r in blk}(x[r,h,:]) @ H_sketch[:,m]
// grid (NBLK, heads), 128 threads
// ---------------------------------------------------------------------------
__global__ void sketch_kernel(const float* __restrict__ x, const float* __restrict__ Hs,
                              float* __restrict__ Sout, int heads, int stride)
{
    int blk = blockIdx.x, h = blockIdx.y;
    int d = threadIdx.x; // 0..127
    __shared__ float mean[DH];
    float acc = 0.f;
    const float* base = x + (size_t)(blk * BLK) * stride + h * DH + d;
    for (int r = 0; r < BLK; r++) acc += base[(size_t)r * stride];
    mean[d] = acc * (1.f / 64.f);
    __syncthreads();
    if (d < MSK) {
        float s = 0.f;
#pragma unroll 16
        for (int dd = 0; dd < DH; dd++) s = fmaf(mean[dd], Hs[dd * MSK + d], s);
        Sout[((size_t)h * NBLK + blk) * MSK + d] = s;
    }
}

// ---------------------------------------------------------------------------
// Block scores + causal mask + diag boost + top-8. grid 16, 64 threads.
// Tie-break: strict '>' picks lowest index among ties (masked -1e9 fillers
// contribute exactly 0 downstream, so selection order is output-invariant).
// ---------------------------------------------------------------------------
__global__ void topk_kernel(const float* __restrict__ Sq, const float* __restrict__ Sk,
                            int* __restrict__ idx_out)
{
    int h = blockIdx.x;
    int qb = threadIdx.x; // 0..63
    int kvh = h >> 2;
    const float* sq = Sq + ((size_t)h * NBLK + qb) * MSK;
    float vals[NBLK];
    for (int j = 0; j < NBLK; j++) {
        if (j > qb)       vals[j] = NEGV;
        else if (j == qb) vals[j] = 1e9f;
        else {
            const float* sk = Sk + ((size_t)kvh * NBLK + j) * MSK;
            float s = 0.f;
#pragma unroll
            for (int m = 0; m < MSK; m++) s = fmaf(sq[m], sk[m], s);
            vals[j] = s;
        }
    }
    for (int t = 0; t < KTOP; t++) {
        float best = -3e9f; int bi = 0;
        for (int j = 0; j < NBLK; j++)
            if (vals[j] > best) { best = vals[j]; bi = j; }
        idx_out[((size_t)h * NBLK + qb) * KTOP + t] = bi;
        vals[bi] = -4e9f;
    }
}

// ---------------------------------------------------------------------------
// Sparse block attention. grid (NBLK, NH), 256 threads.
// smem: Q 64x129, K/V 64x129, scores 64x520  (~199 KB dynamic)
// ---------------------------------------------------------------------------
#define QS 129
#define SS 520
__global__ __launch_bounds__(256, 1)
void attn_kernel(const float* __restrict__ q, const float* __restrict__ k,
                 const float* __restrict__ v, const int* __restrict__ idxs,
                 float* __restrict__ out)
{
    extern __shared__ float sm[];
    float* Qs = sm;                 // 64*129
    float* Ks = Qs + 64 * QS;       // 64*129
    float* Sc = Ks + 64 * QS;       // 64*520
    __shared__ int sel[KTOP];

    const int qb = blockIdx.x, h = blockIdx.y;
    const int kvh = h >> 2;
    const int tid = threadIdx.x;
    const int tx = tid & 15;
    const int ty = tid >> 4;

    for (int i = tid; i < 64 * DH; i += 256) {
        int r = i >> 7, d = i & 127;
        Qs[r * QS + d] = q[(size_t)(qb * BLK + r) * (NH * DH) + h * DH + d];
    }
    if (tid < KTOP) sel[tid] = idxs[((size_t)h * NBLK + qb) * KTOP + tid];
    __syncthreads();

    const float scale = 0.08838834764831845f; // 1/sqrt(128)

    // ---- scores ----
    for (int kb = 0; kb < KTOP; kb++) {
        int jb = sel[kb];
        for (int i = tid; i < 64 * DH; i += 256) {
            int r = i >> 7, d = i & 127;
            Ks[r * QS + d] = k[(size_t)(jb * BLK + r) * (NKV * DH) + kvh * DH + d];
        }
        __syncthreads();
        float acc[4][4];
#pragma unroll
        for (int i = 0; i < 4; i++)
#pragma unroll
            for (int j = 0; j < 4; j++) acc[i][j] = 0.f;
#pragma unroll 4
        for (int d = 0; d < DH; d++) {
            float ar[4], br[4];
#pragma unroll
            for (int i = 0; i < 4; i++) ar[i] = Qs[(ty * 4 + i) * QS + d];
#pragma unroll
            for (int j = 0; j < 4; j++) br[j] = Ks[(tx * 4 + j) * QS + d];
#pragma unroll
            for (int i = 0; i < 4; i++)
#pragma unroll
                for (int j = 0; j < 4; j++) acc[i][j] = fmaf(ar[i], br[j], acc[i][j]);
        }
#pragma unroll
        for (int i = 0; i < 4; i++)
#pragma unroll
            for (int j = 0; j < 4; j++) {
                int qr = ty * 4 + i, kc = tx * 4 + j;
                int kpos = jb * BLK + kc, qpos = qb * BLK + qr;
                Sc[qr * SS + kb * BLK + kc] = (kpos <= qpos) ? acc[i][j] * scale : NEGV;
            }
        __syncthreads();
    }

    // ---- softmax (4 threads/row) ----
    {
        int row = tid >> 2, lane = tid & 3;
        float* srow = Sc + row * SS;
        float mx = -3e30f;
        for (int c = lane; c < KTOP * BLK; c += 4) mx = fmaxf(mx, srow[c]);
        mx = fmaxf(mx, __shfl_xor_sync(0xffffffffu, mx, 1));
        mx = fmaxf(mx, __shfl_xor_sync(0xffffffffu, mx, 2));
        float sum = 0.f;
        for (int c = lane; c < KTOP * BLK; c += 4) {
            float e = expf(srow[c] - mx);
            srow[c] = e;
            sum += e;
        }
        sum += __shfl_xor_sync(0xffffffffu, sum, 1);
        sum += __shfl_xor_sync(0xffffffffu, sum, 2);
        float invs = 1.f / sum;
        for (int c = lane; c < KTOP * BLK; c += 4) srow[c] *= invs;
    }
    __syncthreads();

    // ---- PV: thread owns rows ty*4..+3, cols tx + j*16 ----
    float oacc[4][8];
#pragma unroll
    for (int i = 0; i < 4; i++)
#pragma unroll
        for (int j = 0; j < 8; j++) oacc[i][j] = 0.f;

    for (int kb = 0; kb < KTOP; kb++) {
        int jb = sel[kb];
        for (int i = tid; i < 64 * DH; i += 256) {
            int r = i >> 7, d = i & 127;
            Ks[r * QS + d] = v[(size_t)(jb * BLK + r) * (NKV * DH) + kvh * DH + d];
        }
        __syncthreads();
#pragma unroll 2
        for (int kc = 0; kc < BLK; kc++) {
            float p[4];
#pragma unroll
            for (int i = 0; i < 4; i++) p[i] = Sc[(ty * 4 + i) * SS + kb * BLK + kc];
#pragma unroll
            for (int j = 0; j < 8; j++) {
                float vv = Ks[kc * QS + tx + j * 16];
#pragma unroll
                for (int i = 0; i < 4; i++) oacc[i][j] = fmaf(p[i], vv, oacc[i][j]);
            }
        }
        __syncthreads();
    }

#pragma unroll
    for (int i = 0; i < 4; i++) {
        int qr = ty * 4 + i;
#pragma unroll
        for (int j = 0; j < 8; j++)
            out[(size_t)(qb * BLK + qr) * (NH * DH) + h * DH + tx + j * 16] = oacc[i][j];
    }
}

// ---------------------------------------------------------------------------
extern "C" void kernel_launch(void* const* d_in, const int* in_sizes, int n_in,
                              void* d_out, int out_size)
{
    const float* hs  = (const float*)d_in[0];
    const int*   pos = (const int*)d_in[1];
    const float* Wq  = (const float*)d_in[2];
    const float* Wk  = (const float*)d_in[3];
    const float* Wv  = (const float*)d_in[4];
    const float* Wo  = (const float*)d_in[5];
    const float* Hs  = (const float*)d_in[6];
    float* out = (float*)d_out;

    float *q, *k, *v, *attn, *Sq, *Sk;
    int* idx;
    cudaGetSymbolAddress((void**)&q,    g_q);
    cudaGetSymbolAddress((void**)&k,    g_k);
    cudaGetSymbolAddress((void**)&v,    g_v);
    cudaGetSymbolAddress((void**)&attn, g_attn);
    cudaGetSymbolAddress((void**)&Sq,   g_Sq);
    cudaGetSymbolAddress((void**)&Sk,   g_Sk);
    cudaGetSymbolAddress((void**)&idx,  g_idx);

    static int smem_set = 0;
    const int attn_smem = (64 * QS * 2 + 64 * SS) * (int)sizeof(float);
    if (!smem_set) {
        cudaFuncSetAttribute(attn_kernel, cudaFuncAttributeMaxDynamicSharedMemorySize,
                             attn_smem);
        smem_set = 1;
    }

    // 1. projections
    sgemm128<<<dim3(2048 / 128, S_LEN / 128), 256>>>(hs, Wq, q, S_LEN, 2048, HID);
    sgemm128<<<dim3(512 / 128,  S_LEN / 128), 256>>>(hs, Wk, k, S_LEN, 512, HID);
    sgemm128<<<dim3(512 / 128,  S_LEN / 128), 256>>>(hs, Wv, v, S_LEN, 512, HID);

    // 2. RoPE
    {
        int tq = S_LEN * NH * 64;
        rope_kernel<<<(tq + 255) / 256, 256>>>(q, pos, NH);
        int tk = S_LEN * NKV * 64;
        rope_kernel<<<(tk + 255) / 256, 256>>>(k, pos, NKV);
    }

    // 3. sketches
    sketch_kernel<<<dim3(NBLK, NH),  DH>>>(q, Hs, Sq, NH, NH * DH);
    sketch_kernel<<<dim3(NBLK, NKV), DH>>>(k, Hs, Sk, NKV, NKV * DH);

    // 4. block top-k
    topk_kernel<<<NH, NBLK>>>(Sq, Sk, idx);

    // 5. sparse attention
    attn_kernel<<<dim3(NBLK, NH), 256, attn_smem>>>(q, k, v, idx, attn);

    // 6. output projection
    sgemm128<<<dim3(2048 / 128, S_LEN / 128), 256>>>(attn, Wo, out, S_LEN, 2048, HID);
}

// round 9
// speedup vs baseline: 1.8638x; 1.8638x over previous
#include <cuda_runtime.h>
#include <cuda_bf16.h>
#include <math.h>
#include <stdint.h>
#include <cstdint>

// ---------------------------------------------------------------------------
// SketchWalkLlamaAttention  (B=1, S=4096, HID=2048, NH=16, NKV=4, D=128,
//                            BLK=64, M=32, K_TOP=8, nblk=64)
// R6: fix R5 cp.async staging bug (only half of each operand tile was
//     written -> NaN). Each thread now covers 2 of the 512 16B chunk-slots
//     per K-chunk. GEMM = split-bf16 HMMA (m16n8k16), fp32 accumulators.
// ---------------------------------------------------------------------------

#define S_LEN 4096
#define HID   2048
#define NH    16
#define NKV   4
#define DH    128
#define BLK   64
#define NBLK  64
#define MSK   32
#define KTOP  8
#define NEGV  (-1e9f)

// scratch (device globals: no allocation allowed)
__device__ float g_q[S_LEN * NH * DH];
__device__ float g_k[S_LEN * NKV * DH];
__device__ float g_v[S_LEN * NKV * DH];
__device__ float g_attn[S_LEN * NH * DH];
__device__ float g_Sq[NH * NBLK * MSK];
__device__ float g_Sk[NKV * NBLK * MSK];
__device__ int   g_idx[NH * NBLK * KTOP];
__device__ float g_invf[64];

// bf16 split-precision operand buffers
__device__ __nv_bfloat16 g_xh[S_LEN * HID];
__device__ __nv_bfloat16 g_xl[S_LEN * HID];
__device__ __nv_bfloat16 g_wqTh[2048 * 2048], g_wqTl[2048 * 2048];
__device__ __nv_bfloat16 g_wkTh[512 * 2048],  g_wkTl[512 * 2048];
__device__ __nv_bfloat16 g_wvTh[512 * 2048],  g_wvTl[512 * 2048];
__device__ __nv_bfloat16 g_woTh[2048 * 2048], g_woTl[2048 * 2048];

__device__ __forceinline__ uint32_t smem_u32(const void* p) {
    uint32_t a;
    asm("{ .reg .u64 t; cvta.to.shared.u64 t, %1; cvt.u32.u64 %0, t; }" : "=r"(a) : "l"(p));
    return a;
}

// ---------------------------------------------------------------------------
// fp32 -> (hi, lo) bf16 split, vectorized
// ---------------------------------------------------------------------------
__global__ void split_f32(const float* __restrict__ A, __nv_bfloat16* __restrict__ H,
                          __nv_bfloat16* __restrict__ L, int n4)
{
    int i = blockIdx.x * blockDim.x + threadIdx.x;
    if (i >= n4) return;
    float4 v = ((const float4*)A)[i];
    float f[4] = {v.x, v.y, v.z, v.w};
    __nv_bfloat16 h[4], l[4];
#pragma unroll
    for (int j = 0; j < 4; j++) {
        h[j] = __float2bfloat16(f[j]);
        l[j] = __float2bfloat16(f[j] - __bfloat162float(h[j]));
    }
    ((__nv_bfloat162*)H)[2 * i]     = __nv_bfloat162(h[0], h[1]);
    ((__nv_bfloat162*)H)[2 * i + 1] = __nv_bfloat162(h[2], h[3]);
    ((__nv_bfloat162*)L)[2 * i]     = __nv_bfloat162(l[0], l[1]);
    ((__nv_bfloat162*)L)[2 * i + 1] = __nv_bfloat162(l[2], l[3]);
}

// ---------------------------------------------------------------------------
// W [K,N] fp32 row-major -> T [N,K] bf16 hi/lo
// ---------------------------------------------------------------------------
__global__ void transpose_split(const float* __restrict__ W, __nv_bfloat16* __restrict__ Th,
                                __nv_bfloat16* __restrict__ Tl, int K, int N)
{
    __shared__ float tile[32][33];
    int n0 = blockIdx.x * 32, k0 = blockIdx.y * 32;
    int tx = threadIdx.x, ty = threadIdx.y; // 32 x 8
#pragma unroll
    for (int i = 0; i < 32; i += 8)
        tile[ty + i][tx] = W[(size_t)(k0 + ty + i) * N + n0 + tx];
    __syncthreads();
#pragma unroll
    for (int i = 0; i < 32; i += 8) {
        float v = tile[tx][ty + i];
        __nv_bfloat16 h = __float2bfloat16(v);
        float lo = v - __bfloat162float(h);
        size_t o = (size_t)(n0 + ty + i) * K + k0 + tx;
        Th[o] = h;
        Tl[o] = __float2bfloat16(lo);
    }
}

// ---------------------------------------------------------------------------
// Split-bf16 HMMA GEMM: C[M,N] = A @ B^T
//   A: [M,K] hi/lo bf16 row-major;  B: [N,K] hi/lo bf16 row-major.
//   C = Ah*Bh + Ah*Bl + Al*Bh, fp32 accumulation in registers.
// 128x128 CTA tile, BK=32, 256 threads, 8 warps (2 x 4), warp tile 64x32.
// smem rows padded to 40 halves (80B): 16B-aligned for cp.async AND
// conflict-free for the fragment bank pattern (bank = 20*row + tg covers
// all 32 banks exactly once per 8-row octet).
// ---------------------------------------------------------------------------
#define BK 32
#define ASTRIDE_B 80                      // bytes per smem row (40 halves)
#define TILE_BYTES (128 * ASTRIDE_B)      // 10240
#define BUF_BYTES  (4 * TILE_BYTES)       // 40960 (Ah, Al, Bh, Bl)
#define GEMM_SMEM  (2 * BUF_BYTES)        // 81920 double-buffered

#define MMA16816(c, a, b) \
    asm volatile("mma.sync.aligned.m16n8k16.row.col.f32.bf16.bf16.f32 " \
                 "{%0,%1,%2,%3}, {%4,%5,%6,%7}, {%8,%9}, {%0,%1,%2,%3};" \
                 : "+f"((c)[0]), "+f"((c)[1]), "+f"((c)[2]), "+f"((c)[3]) \
                 : "r"((a)[0]), "r"((a)[1]), "r"((a)[2]), "r"((a)[3]), \
                   "r"((b)[0]), "r"((b)[1]))

// Stage one BK-chunk of all 4 operand tiles. 512 chunk-slots of 16B per
// tile (128 rows x 4 chunks); 256 threads -> 2 slots each.
__device__ __forceinline__ void issue_chunk(
    const __nv_bfloat16* gAh, const __nv_bfloat16* gAl,
    const __nv_bfloat16* gBh, const __nv_bfloat16* gBl,
    int K, int k0, uint32_t sdst, int tid)
{
#pragma unroll
    for (int it = 0; it < 2; it++) {
        int idx = tid + it * 256;
        int r = idx >> 2, cc = idx & 3;
        size_t off = (size_t)r * K + k0 + cc * 8;   // 8 bf16 = 16 bytes
        uint32_t d0 = sdst + r * ASTRIDE_B + cc * 16;
        asm volatile("cp.async.cg.shared.global [%0], [%1], 16;" :: "r"(d0), "l"(gAh + off));
        asm volatile("cp.async.cg.shared.global [%0], [%1], 16;" :: "r"(d0 + TILE_BYTES), "l"(gAl + off));
        asm volatile("cp.async.cg.shared.global [%0], [%1], 16;" :: "r"(d0 + 2 * TILE_BYTES), "l"(gBh + off));
        asm volatile("cp.async.cg.shared.global [%0], [%1], 16;" :: "r"(d0 + 3 * TILE_BYTES), "l"(gBl + off));
    }
    asm volatile("cp.async.commit_group;" ::: "memory");
}

__device__ __forceinline__ void load_a_frag(uint32_t a[4][4], const char* t,
                                            int warp_m, int g, int tg, int k0)
{
#pragma unroll
    for (int mt = 0; mt < 4; mt++) {
        int rb = warp_m * 64 + mt * 16;
        a[mt][0] = *(const uint32_t*)(t + (rb + g)     * ASTRIDE_B + (k0 + tg * 2)     * 2);
        a[mt][1] = *(const uint32_t*)(t + (rb + g + 8) * ASTRIDE_B + (k0 + tg * 2)     * 2);
        a[mt][2] = *(const uint32_t*)(t + (rb + g)     * ASTRIDE_B + (k0 + 8 + tg * 2) * 2);
        a[mt][3] = *(const uint32_t*)(t + (rb + g + 8) * ASTRIDE_B + (k0 + 8 + tg * 2) * 2);
    }
}
__device__ __forceinline__ void load_b_frag(uint32_t b[4][2], const char* t,
                                            int warp_n, int g, int tg, int k0)
{
#pragma unroll
    for (int nt = 0; nt < 4; nt++) {
        int nr = warp_n * 32 + nt * 8 + g;
        b[nt][0] = *(const uint32_t*)(t + nr * ASTRIDE_B + (k0 + tg * 2)     * 2);
        b[nt][1] = *(const uint32_t*)(t + nr * ASTRIDE_B + (k0 + 8 + tg * 2) * 2);
    }
}

__global__ __launch_bounds__(256)
void gemm_split(const __nv_bfloat16* __restrict__ Ah, const __nv_bfloat16* __restrict__ Al,
                const __nv_bfloat16* __restrict__ Bh, const __nv_bfloat16* __restrict__ Bl,
                float* __restrict__ C, int M, int N, int K)
{
    extern __shared__ char dsm[];
    const int tid = threadIdx.x, lane = tid & 31, wid = tid >> 5;
    const int warp_m = wid & 1, warp_n = wid >> 1;
    const int g = lane >> 2, tg = lane & 3;
    const int row0 = blockIdx.y * 128, col0 = blockIdx.x * 128;

    const __nv_bfloat16* gAh = Ah + (size_t)row0 * K;
    const __nv_bfloat16* gAl = Al + (size_t)row0 * K;
    const __nv_bfloat16* gBh = Bh + (size_t)col0 * K;
    const __nv_bfloat16* gBl = Bl + (size_t)col0 * K;
    const uint32_t sbase = smem_u32(dsm);

    float acc[4][4][4];
#pragma unroll
    for (int mt = 0; mt < 4; mt++)
#pragma unroll
        for (int nt = 0; nt < 4; nt++)
#pragma unroll
            for (int e = 0; e < 4; e++) acc[mt][nt][e] = 0.f;

    const int nchunk = K / BK;
    issue_chunk(gAh, gAl, gBh, gBl, K, 0, sbase, tid);

    for (int c = 0; c < nchunk; c++) {
        if (c + 1 < nchunk) {
            issue_chunk(gAh, gAl, gBh, gBl, K, (c + 1) * BK,
                        sbase + ((c + 1) & 1) * BUF_BYTES, tid);
            asm volatile("cp.async.wait_group 1;" ::: "memory");
        } else {
            asm volatile("cp.async.wait_group 0;" ::: "memory");
        }
        __syncthreads();

        const char* bufp = dsm + (c & 1) * BUF_BYTES;
        const char* tAh = bufp;
        const char* tAl = bufp + TILE_BYTES;
        const char* tBh = bufp + 2 * TILE_BYTES;
        const char* tBl = bufp + 3 * TILE_BYTES;

#pragma unroll
        for (int ks = 0; ks < 2; ks++) {
            const int k0 = ks * 16;
            uint32_t a[4][4], bh[4][2], bl[4][2];
            load_a_frag(a, tAh, warp_m, g, tg, k0);     // Ah
            load_b_frag(bh, tBh, warp_n, g, tg, k0);    // Bh
            load_b_frag(bl, tBl, warp_n, g, tg, k0);    // Bl
#pragma unroll
            for (int mt = 0; mt < 4; mt++)
#pragma unroll
                for (int nt = 0; nt < 4; nt++) MMA16816(acc[mt][nt], a[mt], bh[nt]);
#pragma unroll
            for (int mt = 0; mt < 4; mt++)
#pragma unroll
                for (int nt = 0; nt < 4; nt++) MMA16816(acc[mt][nt], a[mt], bl[nt]);
            load_a_frag(a, tAl, warp_m, g, tg, k0);     // Al
#pragma unroll
            for (int mt = 0; mt < 4; mt++)
#pragma unroll
                for (int nt = 0; nt < 4; nt++) MMA16816(acc[mt][nt], a[mt], bh[nt]);
        }
        __syncthreads();
    }

    // epilogue
#pragma unroll
    for (int mt = 0; mt < 4; mt++) {
        int r = row0 + warp_m * 64 + mt * 16 + g;
#pragma unroll
        for (int nt = 0; nt < 4; nt++) {
            int cc = col0 + warp_n * 32 + nt * 8 + tg * 2;
            *(float2*)&C[(size_t)r * N + cc]       = make_float2(acc[mt][nt][0], acc[mt][nt][1]);
            *(float2*)&C[(size_t)(r + 8) * N + cc] = make_float2(acc[mt][nt][2], acc[mt][nt][3]);
        }
    }
}

// ---------------------------------------------------------------------------
// inv_freq table
// ---------------------------------------------------------------------------
__global__ void init_invf()
{
    int i = threadIdx.x;
    if (i < 64) g_invf[i] = (float)exp(-(double)i * 0.14391156831212787); // ln(1e4)/64
}

// ---------------------------------------------------------------------------
// RoPE in place: x is (S, H, 128). H = NH for q, NKV for k.
// ---------------------------------------------------------------------------
__global__ void rope_kernel(float* __restrict__ x, const int* __restrict__ pos, int H)
{
    int i = blockIdx.x * blockDim.x + threadIdx.x;
    int total = S_LEN * H * 64;
    if (i >= total) return;
    int half = i & 63;
    int sh = i >> 6;
    int s = sh / H;
    float p = (float)pos[s];
    float ang = p * g_invf[half];
    float sn, cs;
    sincosf(ang, &sn, &cs);
    float* base = x + (size_t)sh * DH;
    float x1 = base[half];
    float x2 = base[half + 64];
    base[half]      = x1 * cs - x2 * sn;
    base[half + 64] = x2 * cs + x1 * sn;
}

// ---------------------------------------------------------------------------
// Sketch: Sout[h][blk][m] = mean_{r in blk}(x[r,h,:]) @ H_sketch[:,m]
// ---------------------------------------------------------------------------
__global__ void sketch_kernel(const float* __restrict__ x, const float* __restrict__ Hs,
                              float* __restrict__ Sout, int heads, int stride)
{
    int blk = blockIdx.x, h = blockIdx.y;
    int d = threadIdx.x; // 0..127
    __shared__ float mean[DH];
    float acc = 0.f;
    const float* base = x + (size_t)(blk * BLK) * stride + h * DH + d;
    for (int r = 0; r < BLK; r++) acc += base[(size_t)r * stride];
    mean[d] = acc * (1.f / 64.f);
    __syncthreads();
    if (d < MSK) {
        float s = 0.f;
#pragma unroll 16
        for (int dd = 0; dd < DH; dd++) s = fmaf(mean[dd], Hs[dd * MSK + d], s);
        Sout[((size_t)h * NBLK + blk) * MSK + d] = s;
    }
}

// ---------------------------------------------------------------------------
// Block scores + causal mask + diag boost + top-8.
// ---------------------------------------------------------------------------
__global__ void topk_kernel(const float* __restrict__ Sq, const float* __restrict__ Sk,
                            int* __restrict__ idx_out)
{
    int h = blockIdx.x;
    int qb = threadIdx.x; // 0..63
    int kvh = h >> 2;
    const float* sq = Sq + ((size_t)h * NBLK + qb) * MSK;
    float vals[NBLK];
    for (int j = 0; j < NBLK; j++) {
        if (j > qb)       vals[j] = NEGV;
        else if (j == qb) vals[j] = 1e9f;
        else {
            const float* sk = Sk + ((size_t)kvh * NBLK + j) * MSK;
            float s = 0.f;
#pragma unroll
            for (int m = 0; m < MSK; m++) s = fmaf(sq[m], sk[m], s);
            vals[j] = s;
        }
    }
    for (int t = 0; t < KTOP; t++) {
        float best = -3e9f; int bi = 0;
        for (int j = 0; j < NBLK; j++)
            if (vals[j] > best) { best = vals[j]; bi = j; }
        idx_out[((size_t)h * NBLK + qb) * KTOP + t] = bi;
        vals[bi] = -4e9f;
    }
}

// ---------------------------------------------------------------------------
// Sparse block attention. grid (NBLK, NH), 256 threads.
// ---------------------------------------------------------------------------
#define QS 129
#define SS 520
__global__ __launch_bounds__(256, 1)
void attn_kernel(const float* __restrict__ q, const float* __restrict__ k,
                 const float* __restrict__ v, const int* __restrict__ idxs,
                 float* __restrict__ out)
{
    extern __shared__ float sm[];
    float* Qs = sm;                 // 64*129
    float* Ks = Qs + 64 * QS;       // 64*129
    float* Sc = Ks + 64 * QS;       // 64*520
    __shared__ int sel[KTOP];

    const int qb = blockIdx.x, h = blockIdx.y;
    const int kvh = h >> 2;
    const int tid = threadIdx.x;
    const int tx = tid & 15;
    const int ty = tid >> 4;

    for (int i = tid; i < 64 * DH; i += 256) {
        int r = i >> 7, d = i & 127;
        Qs[r * QS + d] = q[(size_t)(qb * BLK + r) * (NH * DH) + h * DH + d];
    }
    if (tid < KTOP) sel[tid] = idxs[((size_t)h * NBLK + qb) * KTOP + tid];
    __syncthreads();

    const float scale = 0.08838834764831845f; // 1/sqrt(128)

    for (int kb = 0; kb < KTOP; kb++) {
        int jb = sel[kb];
        for (int i = tid; i < 64 * DH; i += 256) {
            int r = i >> 7, d = i & 127;
            Ks[r * QS + d] = k[(size_t)(jb * BLK + r) * (NKV * DH) + kvh * DH + d];
        }
        __syncthreads();
        float acc[4][4];
#pragma unroll
        for (int i = 0; i < 4; i++)
#pragma unroll
            for (int j = 0; j < 4; j++) acc[i][j] = 0.f;
#pragma unroll 4
        for (int d = 0; d < DH; d++) {
            float ar[4], br[4];
#pragma unroll
            for (int i = 0; i < 4; i++) ar[i] = Qs[(ty * 4 + i) * QS + d];
#pragma unroll
            for (int j = 0; j < 4; j++) br[j] = Ks[(tx * 4 + j) * QS + d];
#pragma unroll
            for (int i = 0; i < 4; i++)
#pragma unroll
                for (int j = 0; j < 4; j++) acc[i][j] = fmaf(ar[i], br[j], acc[i][j]);
        }
#pragma unroll
        for (int i = 0; i < 4; i++)
#pragma unroll
            for (int j = 0; j < 4; j++) {
                int qr = ty * 4 + i, kc = tx * 4 + j;
                int kpos = jb * BLK + kc, qpos = qb * BLK + qr;
                Sc[qr * SS + kb * BLK + kc] = (kpos <= qpos) ? acc[i][j] * scale : NEGV;
            }
        __syncthreads();
    }

    {
        int row = tid >> 2, lane = tid & 3;
        float* srow = Sc + row * SS;
        float mx = -3e30f;
        for (int c = lane; c < KTOP * BLK; c += 4) mx = fmaxf(mx, srow[c]);
        mx = fmaxf(mx, __shfl_xor_sync(0xffffffffu, mx, 1));
        mx = fmaxf(mx, __shfl_xor_sync(0xffffffffu, mx, 2));
        float sum = 0.f;
        for (int c = lane; c < KTOP * BLK; c += 4) {
            float e = expf(srow[c] - mx);
            srow[c] = e;
            sum += e;
        }
        sum += __shfl_xor_sync(0xffffffffu, sum, 1);
        sum += __shfl_xor_sync(0xffffffffu, sum, 2);
        float invs = 1.f / sum;
        for (int c = lane; c < KTOP * BLK; c += 4) srow[c] *= invs;
    }
    __syncthreads();

    float oacc[4][8];
#pragma unroll
    for (int i = 0; i < 4; i++)
#pragma unroll
        for (int j = 0; j < 8; j++) oacc[i][j] = 0.f;

    for (int kb = 0; kb < KTOP; kb++) {
        int jb = sel[kb];
        for (int i = tid; i < 64 * DH; i += 256) {
            int r = i >> 7, d = i & 127;
            Ks[r * QS + d] = v[(size_t)(jb * BLK + r) * (NKV * DH) + kvh * DH + d];
        }
        __syncthreads();
#pragma unroll 2
        for (int kc = 0; kc < BLK; kc++) {
            float p[4];
#pragma unroll
            for (int i = 0; i < 4; i++) p[i] = Sc[(ty * 4 + i) * SS + kb * BLK + kc];
#pragma unroll
            for (int j = 0; j < 8; j++) {
                float vv = Ks[kc * QS + tx + j * 16];
#pragma unroll
                for (int i = 0; i < 4; i++) oacc[i][j] = fmaf(p[i], vv, oacc[i][j]);
            }
        }
        __syncthreads();
    }

#pragma unroll
    for (int i = 0; i < 4; i++) {
        int qr = ty * 4 + i;
#pragma unroll
        for (int j = 0; j < 8; j++)
            out[(size_t)(qb * BLK + qr) * (NH * DH) + h * DH + tx + j * 16] = oacc[i][j];
    }
}

// ---------------------------------------------------------------------------
extern "C" void kernel_launch(void* const* d_in, const int* in_sizes, int n_in,
                              void* d_out, int out_size)
{
    const float* hs  = (const float*)d_in[0];
    const int*   pos = (const int*)d_in[1];
    const float* Wq  = (const float*)d_in[2];
    const float* Wk  = (const float*)d_in[3];
    const float* Wv  = (const float*)d_in[4];
    const float* Wo  = (const float*)d_in[5];
    const float* Hs  = (const float*)d_in[6];
    float* out = (float*)d_out;

    float *q, *k, *v, *attn, *Sq, *Sk;
    int* idx;
    __nv_bfloat16 *xh, *xl, *wqh, *wql, *wkh, *wkl, *wvh, *wvl, *woh, *wol;
    cudaGetSymbolAddress((void**)&q,    g_q);
    cudaGetSymbolAddress((void**)&k,    g_k);
    cudaGetSymbolAddress((void**)&v,    g_v);
    cudaGetSymbolAddress((void**)&attn, g_attn);
    cudaGetSymbolAddress((void**)&Sq,   g_Sq);
    cudaGetSymbolAddress((void**)&Sk,   g_Sk);
    cudaGetSymbolAddress((void**)&idx,  g_idx);
    cudaGetSymbolAddress((void**)&xh,   g_xh);
    cudaGetSymbolAddress((void**)&xl,   g_xl);
    cudaGetSymbolAddress((void**)&wqh,  g_wqTh);
    cudaGetSymbolAddress((void**)&wql,  g_wqTl);
    cudaGetSymbolAddress((void**)&wkh,  g_wkTh);
    cudaGetSymbolAddress((void**)&wkl,  g_wkTl);
    cudaGetSymbolAddress((void**)&wvh,  g_wvTh);
    cudaGetSymbolAddress((void**)&wvl,  g_wvTl);
    cudaGetSymbolAddress((void**)&woh,  g_woTh);
    cudaGetSymbolAddress((void**)&wol,  g_woTl);

    const int attn_smem = (64 * QS * 2 + 64 * SS) * (int)sizeof(float);
    cudaFuncSetAttribute(attn_kernel, cudaFuncAttributeMaxDynamicSharedMemorySize, attn_smem);
    cudaFuncSetAttribute(gemm_split, cudaFuncAttributeMaxDynamicSharedMemorySize, GEMM_SMEM);

    init_invf<<<1, 64>>>();

    // split activations, transpose+split weights
    split_f32<<<(S_LEN * HID / 4 + 255) / 256, 256>>>(hs, xh, xl, S_LEN * HID / 4);
    transpose_split<<<dim3(2048 / 32, 2048 / 32), dim3(32, 8)>>>(Wq, wqh, wql, 2048, 2048);
    transpose_split<<<dim3(512 / 32,  2048 / 32), dim3(32, 8)>>>(Wk, wkh, wkl, 2048, 512);
    transpose_split<<<dim3(512 / 32,  2048 / 32), dim3(32, 8)>>>(Wv, wvh, wvl, 2048, 512);
    transpose_split<<<dim3(2048 / 32, 2048 / 32), dim3(32, 8)>>>(Wo, woh, wol, 2048, 2048);

    // projections (split-bf16 HMMA)
    gemm_split<<<dim3(2048 / 128, S_LEN / 128), 256, GEMM_SMEM>>>(xh, xl, wqh, wql, q, S_LEN, 2048, HID);
    gemm_split<<<dim3(512 / 128,  S_LEN / 128), 256, GEMM_SMEM>>>(xh, xl, wkh, wkl, k, S_LEN, 512, HID);
    gemm_split<<<dim3(512 / 128,  S_LEN / 128), 256, GEMM_SMEM>>>(xh, xl, wvh, wvl, v, S_LEN, 512, HID);

    // RoPE
    rope_kernel<<<(S_LEN * NH * 64 + 255) / 256, 256>>>(q, pos, NH);
    rope_kernel<<<(S_LEN * NKV * 64 + 255) / 256, 256>>>(k, pos, NKV);

    // sketches + top-k
    sketch_kernel<<<dim3(NBLK, NH),  DH>>>(q, Hs, Sq, NH, NH * DH);
    sketch_kernel<<<dim3(NBLK, NKV), DH>>>(k, Hs, Sk, NKV, NKV * DH);
    topk_kernel<<<NH, NBLK>>>(Sq, Sk, idx);

    // sparse attention
    attn_kernel<<<dim3(NBLK, NH), 256, attn_smem>>>(q, k, v, idx, attn);

    // output projection
    split_f32<<<(S_LEN * HID / 4 + 255) / 256, 256>>>(attn, xh, xl, S_LEN * HID / 4);
    gemm_split<<<dim3(2048 / 128, S_LEN / 128), 256, GEMM_SMEM>>>(xh, xl, woh, wol, out, S_LEN, 2048, HID);
}

// round 14
// speedup vs baseline: 2.1498x; 1.1535x over previous
#include <cuda_runtime.h>
#include <cuda_bf16.h>
#include <math.h>
#include <stdint.h>
#include <cstdint>

// ---------------------------------------------------------------------------
// SketchWalkLlamaAttention  (B=1, S=4096, HID=2048, NH=16, NKV=4, D=128,
//                            BLK=64, M=32, K_TOP=8, nblk=64)
// R9: gemm_split fragment loads via ldmatrix.x4 (48 LDS -> 12 LDSM per
//     k16-step); attention QK inner loop vectorized (float4 over d, strided
//     K-column mapping for conflict-freedom), float4 tile fills.
// ---------------------------------------------------------------------------

#define S_LEN 4096
#define HID   2048
#define NH    16
#define NKV   4
#define DH    128
#define BLK   64
#define NBLK  64
#define MSK   32
#define KTOP  8
#define NEGV  (-1e9f)

// scratch (device globals: no allocation allowed)
__device__ float g_q[S_LEN * NH * DH];
__device__ float g_k[S_LEN * NKV * DH];
__device__ float g_v[S_LEN * NKV * DH];
__device__ float g_attn[S_LEN * NH * DH];
__device__ float g_Sq[NH * NBLK * MSK];
__device__ float g_Sk[NKV * NBLK * MSK];
__device__ int   g_idx[NH * NBLK * KTOP];
__device__ float g_invf[64];

// bf16 split-precision operand buffers
__device__ __nv_bfloat16 g_xh[S_LEN * HID];
__device__ __nv_bfloat16 g_xl[S_LEN * HID];
__device__ __nv_bfloat16 g_wqTh[2048 * 2048], g_wqTl[2048 * 2048];
__device__ __nv_bfloat16 g_wkTh[512 * 2048],  g_wkTl[512 * 2048];
__device__ __nv_bfloat16 g_wvTh[512 * 2048],  g_wvTl[512 * 2048];
__device__ __nv_bfloat16 g_woTh[2048 * 2048], g_woTl[2048 * 2048];

__device__ __forceinline__ uint32_t smem_u32(const void* p) {
    uint32_t a;
    asm("{ .reg .u64 t; cvta.to.shared.u64 t, %1; cvt.u32.u64 %0, t; }" : "=r"(a) : "l"(p));
    return a;
}

// ---------------------------------------------------------------------------
// fp32 -> (hi, lo) bf16 split, vectorized
// ---------------------------------------------------------------------------
__global__ void split_f32(const float* __restrict__ A, __nv_bfloat16* __restrict__ H,
                          __nv_bfloat16* __restrict__ L, int n4)
{
    int i = blockIdx.x * blockDim.x + threadIdx.x;
    if (i >= n4) return;
    float4 v = ((const float4*)A)[i];
    float f[4] = {v.x, v.y, v.z, v.w};
    __nv_bfloat16 h[4], l[4];
#pragma unroll
    for (int j = 0; j < 4; j++) {
        h[j] = __float2bfloat16(f[j]);
        l[j] = __float2bfloat16(f[j] - __bfloat162float(h[j]));
    }
    ((__nv_bfloat162*)H)[2 * i]     = __nv_bfloat162(h[0], h[1]);
    ((__nv_bfloat162*)H)[2 * i + 1] = __nv_bfloat162(h[2], h[3]);
    ((__nv_bfloat162*)L)[2 * i]     = __nv_bfloat162(l[0], l[1]);
    ((__nv_bfloat162*)L)[2 * i + 1] = __nv_bfloat162(l[2], l[3]);
}

// ---------------------------------------------------------------------------
// W [K,N] fp32 row-major -> T [N,K] bf16 hi/lo
// ---------------------------------------------------------------------------
__global__ void transpose_split(const float* __restrict__ W, __nv_bfloat16* __restrict__ Th,
                                __nv_bfloat16* __restrict__ Tl, int K, int N)
{
    __shared__ float tile[32][33];
    int n0 = blockIdx.x * 32, k0 = blockIdx.y * 32;
    int tx = threadIdx.x, ty = threadIdx.y; // 32 x 8
#pragma unroll
    for (int i = 0; i < 32; i += 8)
        tile[ty + i][tx] = W[(size_t)(k0 + ty + i) * N + n0 + tx];
    __syncthreads();
#pragma unroll
    for (int i = 0; i < 32; i += 8) {
        float v = tile[tx][ty + i];
        __nv_bfloat16 h = __float2bfloat16(v);
        float lo = v - __bfloat162float(h);
        size_t o = (size_t)(n0 + ty + i) * K + k0 + tx;
        Th[o] = h;
        Tl[o] = __float2bfloat16(lo);
    }
}

// ---------------------------------------------------------------------------
// Split-bf16 HMMA GEMM: C[M,N] = A @ B^T, fragments via ldmatrix.
// 128x128 CTA tile, BK=32, 256 threads, 8 warps (2 x 4), warp tile 64x32.
// smem rows 80B: 16B-aligned, conflict-free for ldmatrix (20-word row
// stride covers all 32 banks exactly once per 8-row phase).
// ---------------------------------------------------------------------------
#define BK 32
#define ASTRIDE_B 80                      // bytes per smem row (40 halves)
#define TILE_BYTES (128 * ASTRIDE_B)      // 10240
#define BUF_BYTES  (4 * TILE_BYTES)       // 40960 (Ah, Al, Bh, Bl)
#define GEMM_SMEM  (2 * BUF_BYTES)        // 81920 double-buffered

#define MMA16816(c, a, b) \
    asm volatile("mma.sync.aligned.m16n8k16.row.col.f32.bf16.bf16.f32 " \
                 "{%0,%1,%2,%3}, {%4,%5,%6,%7}, {%8,%9}, {%0,%1,%2,%3};" \
                 : "+f"((c)[0]), "+f"((c)[1]), "+f"((c)[2]), "+f"((c)[3]) \
                 : "r"((a)[0]), "r"((a)[1]), "r"((a)[2]), "r"((a)[3]), \
                   "r"((b)[0]), "r"((b)[1]))

__device__ __forceinline__ void ldsm_x4(uint32_t r[4], uint32_t addr) {
    asm volatile("ldmatrix.sync.aligned.m8n8.x4.shared.b16 {%0,%1,%2,%3}, [%4];"
                 : "=r"(r[0]), "=r"(r[1]), "=r"(r[2]), "=r"(r[3]) : "r"(addr));
}

// Stage one BK-chunk of all 4 operand tiles: 512 x 16B slots per tile,
// 256 threads -> 2 slots each.
__device__ __forceinline__ void issue_chunk(
    const __nv_bfloat16* gAh, const __nv_bfloat16* gAl,
    const __nv_bfloat16* gBh, const __nv_bfloat16* gBl,
    int K, int k0, uint32_t sdst, int tid)
{
#pragma unroll
    for (int it = 0; it < 2; it++) {
        int idx = tid + it * 256;
        int r = idx >> 2, cc = idx & 3;
        size_t off = (size_t)r * K + k0 + cc * 8;   // 8 bf16 = 16 bytes
        uint32_t d0 = sdst + r * ASTRIDE_B + cc * 16;
        asm volatile("cp.async.cg.shared.global [%0], [%1], 16;" :: "r"(d0), "l"(gAh + off));
        asm volatile("cp.async.cg.shared.global [%0], [%1], 16;" :: "r"(d0 + TILE_BYTES), "l"(gAl + off));
        asm volatile("cp.async.cg.shared.global [%0], [%1], 16;" :: "r"(d0 + 2 * TILE_BYTES), "l"(gBh + off));
        asm volatile("cp.async.cg.shared.global [%0], [%1], 16;" :: "r"(d0 + 3 * TILE_BYTES), "l"(gBl + off));
    }
    asm volatile("cp.async.commit_group;" ::: "memory");
}

__global__ __launch_bounds__(256)
void gemm_split(const __nv_bfloat16* __restrict__ Ah, const __nv_bfloat16* __restrict__ Al,
                const __nv_bfloat16* __restrict__ Bh, const __nv_bfloat16* __restrict__ Bl,
                float* __restrict__ C, int M, int N, int K)
{
    extern __shared__ char dsm[];
    const int tid = threadIdx.x, lane = tid & 31, wid = tid >> 5;
    const int warp_m = wid & 1, warp_n = wid >> 1;
    const int g = lane >> 2, tg = lane & 3;
    const int row0 = blockIdx.y * 128, col0 = blockIdx.x * 128;

    // ldmatrix per-lane addressing
    const int arow  = lane & 15;              // A: lanes 0-15 rows, 16-31 rows (+16B col)
    const int acol  = (lane >> 4) * 16;
    const int brow  = ((lane >> 4) << 3) | (lane & 7);   // B: 8-row pairs
    const int bcol  = ((lane >> 3) & 1) * 16;

    const __nv_bfloat16* gAh = Ah + (size_t)row0 * K;
    const __nv_bfloat16* gAl = Al + (size_t)row0 * K;
    const __nv_bfloat16* gBh = Bh + (size_t)col0 * K;
    const __nv_bfloat16* gBl = Bl + (size_t)col0 * K;
    const uint32_t sbase = smem_u32(dsm);

    float acc[4][4][4];
#pragma unroll
    for (int mt = 0; mt < 4; mt++)
#pragma unroll
        for (int nt = 0; nt < 4; nt++)
#pragma unroll
            for (int e = 0; e < 4; e++) acc[mt][nt][e] = 0.f;

    const int nchunk = K / BK;
    issue_chunk(gAh, gAl, gBh, gBl, K, 0, sbase, tid);

    for (int c = 0; c < nchunk; c++) {
        if (c + 1 < nchunk) {
            issue_chunk(gAh, gAl, gBh, gBl, K, (c + 1) * BK,
                        sbase + ((c + 1) & 1) * BUF_BYTES, tid);
            asm volatile("cp.async.wait_group 1;" ::: "memory");
        } else {
            asm volatile("cp.async.wait_group 0;" ::: "memory");
        }
        __syncthreads();

        const uint32_t bufu = sbase + (c & 1) * BUF_BYTES;
        const uint32_t tAh = bufu;
        const uint32_t tAl = bufu + TILE_BYTES;
        const uint32_t tBh = bufu + 2 * TILE_BYTES;
        const uint32_t tBl = bufu + 3 * TILE_BYTES;

#pragma unroll
        for (int ks = 0; ks < 2; ks++) {
            const int kb = ks * 32;           // byte offset of k16-step
            uint32_t a[4][4], bh[4][2], bl[4][2];
#pragma unroll
            for (int mt = 0; mt < 4; mt++)
                ldsm_x4(a[mt], tAh + (warp_m * 64 + mt * 16 + arow) * ASTRIDE_B + kb + acol);
#pragma unroll
            for (int p = 0; p < 2; p++) {
                uint32_t t[4];
                ldsm_x4(t, tBh + (warp_n * 32 + p * 16 + brow) * ASTRIDE_B + kb + bcol);
                bh[2 * p][0] = t[0]; bh[2 * p][1] = t[1];
                bh[2 * p + 1][0] = t[2]; bh[2 * p + 1][1] = t[3];
            }
#pragma unroll
            for (int p = 0; p < 2; p++) {
                uint32_t t[4];
                ldsm_x4(t, tBl + (warp_n * 32 + p * 16 + brow) * ASTRIDE_B + kb + bcol);
                bl[2 * p][0] = t[0]; bl[2 * p][1] = t[1];
                bl[2 * p + 1][0] = t[2]; bl[2 * p + 1][1] = t[3];
            }
#pragma unroll
            for (int mt = 0; mt < 4; mt++)
#pragma unroll
                for (int nt = 0; nt < 4; nt++) MMA16816(acc[mt][nt], a[mt], bh[nt]);
#pragma unroll
            for (int mt = 0; mt < 4; mt++)
#pragma unroll
                for (int nt = 0; nt < 4; nt++) MMA16816(acc[mt][nt], a[mt], bl[nt]);
#pragma unroll
            for (int mt = 0; mt < 4; mt++)
                ldsm_x4(a[mt], tAl + (warp_m * 64 + mt * 16 + arow) * ASTRIDE_B + kb + acol);
#pragma unroll
            for (int mt = 0; mt < 4; mt++)
#pragma unroll
                for (int nt = 0; nt < 4; nt++) MMA16816(acc[mt][nt], a[mt], bh[nt]);
        }
        __syncthreads();
    }

    // epilogue
#pragma unroll
    for (int mt = 0; mt < 4; mt++) {
        int r = row0 + warp_m * 64 + mt * 16 + g;
#pragma unroll
        for (int nt = 0; nt < 4; nt++) {
            int cc = col0 + warp_n * 32 + nt * 8 + tg * 2;
            *(float2*)&C[(size_t)r * N + cc]       = make_float2(acc[mt][nt][0], acc[mt][nt][1]);
            *(float2*)&C[(size_t)(r + 8) * N + cc] = make_float2(acc[mt][nt][2], acc[mt][nt][3]);
        }
    }
}

// ---------------------------------------------------------------------------
// inv_freq table
// ---------------------------------------------------------------------------
__global__ void init_invf()
{
    int i = threadIdx.x;
    if (i < 64) g_invf[i] = (float)exp(-(double)i * 0.14391156831212787); // ln(1e4)/64
}

// ---------------------------------------------------------------------------
// RoPE in place: x is (S, H, 128). H = NH for q, NKV for k.
// ---------------------------------------------------------------------------
__global__ void rope_kernel(float* __restrict__ x, const int* __restrict__ pos, int H)
{
    int i = blockIdx.x * blockDim.x + threadIdx.x;
    int total = S_LEN * H * 64;
    if (i >= total) return;
    int half = i & 63;
    int sh = i >> 6;
    int s = sh / H;
    float p = (float)pos[s];
    float ang = p * g_invf[half];
    float sn, cs;
    sincosf(ang, &sn, &cs);
    float* base = x + (size_t)sh * DH;
    float x1 = base[half];
    float x2 = base[half + 64];
    base[half]      = x1 * cs - x2 * sn;
    base[half + 64] = x2 * cs + x1 * sn;
}

// ---------------------------------------------------------------------------
// Sketch: Sout[h][blk][m] = mean_{r in blk}(x[r,h,:]) @ H_sketch[:,m]
// ---------------------------------------------------------------------------
__global__ void sketch_kernel(const float* __restrict__ x, const float* __restrict__ Hs,
                              float* __restrict__ Sout, int heads, int stride)
{
    int blk = blockIdx.x, h = blockIdx.y;
    int d = threadIdx.x; // 0..127
    __shared__ float mean[DH];
    float acc = 0.f;
    const float* base = x + (size_t)(blk * BLK) * stride + h * DH + d;
    for (int r = 0; r < BLK; r++) acc += base[(size_t)r * stride];
    mean[d] = acc * (1.f / 64.f);
    __syncthreads();
    if (d < MSK) {
        float s = 0.f;
#pragma unroll 16
        for (int dd = 0; dd < DH; dd++) s = fmaf(mean[dd], Hs[dd * MSK + d], s);
        Sout[((size_t)h * NBLK + blk) * MSK + d] = s;
    }
}

// ---------------------------------------------------------------------------
// Block scores + causal mask + diag boost + top-8.
// ---------------------------------------------------------------------------
__global__ void topk_kernel(const float* __restrict__ Sq, const float* __restrict__ Sk,
                            int* __restrict__ idx_out)
{
    int h = blockIdx.x;
    int qb = threadIdx.x; // 0..63
    int kvh = h >> 2;
    const float* sq = Sq + ((size_t)h * NBLK + qb) * MSK;
    float vals[NBLK];
    for (int j = 0; j < NBLK; j++) {
        if (j > qb)       vals[j] = NEGV;
        else if (j == qb) vals[j] = 1e9f;
        else {
            const float* sk = Sk + ((size_t)kvh * NBLK + j) * MSK;
            float s = 0.f;
#pragma unroll
            for (int m = 0; m < MSK; m++) s = fmaf(sq[m], sk[m], s);
            vals[j] = s;
        }
    }
    for (int t = 0; t < KTOP; t++) {
        float best = -3e9f; int bi = 0;
        for (int j = 0; j < NBLK; j++)
            if (vals[j] > best) { best = vals[j]; bi = j; }
        idx_out[((size_t)h * NBLK + qb) * KTOP + t] = bi;
        vals[bi] = -4e9f;
    }
}

// ---------------------------------------------------------------------------
// Sparse block attention. grid (NBLK, NH), 256 threads.
// QS=132 (16B-aligned rows). QK inner loop float4 over d; K-columns mapped
// kc = tx + 16*j (2-way smem conflicts max). Sc layout absolute, so softmax
// and PV are unchanged.
// ---------------------------------------------------------------------------
#define QS 132
#define SS 520
__global__ __launch_bounds__(256, 1)
void attn_kernel(const float* __restrict__ q, const float* __restrict__ k,
                 const float* __restrict__ v, const int* __restrict__ idxs,
                 float* __restrict__ out)
{
    extern __shared__ float sm[];
    float* Qs = sm;                 // 64*132
    float* Ks = Qs + 64 * QS;       // 64*132
    float* Sc = Ks + 64 * QS;       // 64*520
    __shared__ int sel[KTOP];

    const int qb = blockIdx.x, h = blockIdx.y;
    const int kvh = h >> 2;
    const int tid = threadIdx.x;
    const int tx = tid & 15;
    const int ty = tid >> 4;

    // Q fill (float4): 2048 vec4 slots
    for (int idx = tid; idx < 64 * 32; idx += 256) {
        int r = idx >> 5, u = idx & 31;
        *(float4*)&Qs[r * QS + u * 4] =
            *(const float4*)&q[(size_t)(qb * BLK + r) * (NH * DH) + h * DH + u * 4];
    }
    if (tid < KTOP) sel[tid] = idxs[((size_t)h * NBLK + qb) * KTOP + tid];
    __syncthreads();

    const float scale = 0.08838834764831845f; // 1/sqrt(128)

    // ---- scores ----
    for (int kb = 0; kb < KTOP; kb++) {
        int jb = sel[kb];
        for (int idx = tid; idx < 64 * 32; idx += 256) {
            int r = idx >> 5, u = idx & 31;
            *(float4*)&Ks[r * QS + u * 4] =
                *(const float4*)&k[(size_t)(jb * BLK + r) * (NKV * DH) + kvh * DH + u * 4];
        }
        __syncthreads();
        float acc[4][4];
#pragma unroll
        for (int i = 0; i < 4; i++)
#pragma unroll
            for (int j = 0; j < 4; j++) acc[i][j] = 0.f;
#pragma unroll 4
        for (int d = 0; d < DH; d += 4) {
            float4 ar[4], br[4];
#pragma unroll
            for (int i = 0; i < 4; i++) ar[i] = *(const float4*)&Qs[(ty * 4 + i) * QS + d];
#pragma unroll
            for (int j = 0; j < 4; j++) br[j] = *(const float4*)&Ks[(tx + 16 * j) * QS + d];
#pragma unroll
            for (int i = 0; i < 4; i++)
#pragma unroll
                for (int j = 0; j < 4; j++) {
                    acc[i][j] = fmaf(ar[i].x, br[j].x, acc[i][j]);
                    acc[i][j] = fmaf(ar[i].y, br[j].y, acc[i][j]);
                    acc[i][j] = fmaf(ar[i].z, br[j].z, acc[i][j]);
                    acc[i][j] = fmaf(ar[i].w, br[j].w, acc[i][j]);
                }
        }
#pragma unroll
        for (int i = 0; i < 4; i++)
#pragma unroll
            for (int j = 0; j < 4; j++) {
                int qr = ty * 4 + i, kc = tx + 16 * j;
                int kpos = jb * BLK + kc, qpos = qb * BLK + qr;
                Sc[qr * SS + kb * BLK + kc] = (kpos <= qpos) ? acc[i][j] * scale : NEGV;
            }
        __syncthreads();
    }

    // ---- softmax (4 threads/row) ----
    {
        int row = tid >> 2, lane = tid & 3;
        float* srow = Sc + row * SS;
        float mx = -3e30f;
        for (int c = lane; c < KTOP * BLK; c += 4) mx = fmaxf(mx, srow[c]);
        mx = fmaxf(mx, __shfl_xor_sync(0xffffffffu, mx, 1));
        mx = fmaxf(mx, __shfl_xor_sync(0xffffffffu, mx, 2));
        float sum = 0.f;
        for (int c = lane; c < KTOP * BLK; c += 4) {
            float e = expf(srow[c] - mx);
            srow[c] = e;
            sum += e;
        }
        sum += __shfl_xor_sync(0xffffffffu, sum, 1);
        sum += __shfl_xor_sync(0xffffffffu, sum, 2);
        float invs = 1.f / sum;
        for (int c = lane; c < KTOP * BLK; c += 4) srow[c] *= invs;
    }
    __syncthreads();

    // ---- PV ----
    float oacc[4][8];
#pragma unroll
    for (int i = 0; i < 4; i++)
#pragma unroll
        for (int j = 0; j < 8; j++) oacc[i][j] = 0.f;

    for (int kb = 0; kb < KTOP; kb++) {
        int jb = sel[kb];
        for (int idx = tid; idx < 64 * 32; idx += 256) {
            int r = idx >> 5, u = idx & 31;
            *(float4*)&Ks[r * QS + u * 4] =
                *(const float4*)&v[(size_t)(jb * BLK + r) * (NKV * DH) + kvh * DH + u * 4];
        }
        __syncthreads();
#pragma unroll 2
        for (int kc = 0; kc < BLK; kc++) {
            float p[4];
#pragma unroll
            for (int i = 0; i < 4; i++) p[i] = Sc[(ty * 4 + i) * SS + kb * BLK + kc];
#pragma unroll
            for (int j = 0; j < 8; j++) {
                float vv = Ks[kc * QS + tx + j * 16];
#pragma unroll
                for (int i = 0; i < 4; i++) oacc[i][j] = fmaf(p[i], vv, oacc[i][j]);
            }
        }
        __syncthreads();
    }

#pragma unroll
    for (int i = 0; i < 4; i++) {
        int qr = ty * 4 + i;
#pragma unroll
        for (int j = 0; j < 8; j++)
            out[(size_t)(qb * BLK + qr) * (NH * DH) + h * DH + tx + j * 16] = oacc[i][j];
    }
}

// ---------------------------------------------------------------------------
extern "C" void kernel_launch(void* const* d_in, const int* in_sizes, int n_in,
                              void* d_out, int out_size)
{
    const float* hs  = (const float*)d_in[0];
    const int*   pos = (const int*)d_in[1];
    const float* Wq  = (const float*)d_in[2];
    const float* Wk  = (const float*)d_in[3];
    const float* Wv  = (const float*)d_in[4];
    const float* Wo  = (const float*)d_in[5];
    const float* Hs  = (const float*)d_in[6];
    float* out = (float*)d_out;

    float *q, *k, *v, *attn, *Sq, *Sk;
    int* idx;
    __nv_bfloat16 *xh, *xl, *wqh, *wql, *wkh, *wkl, *wvh, *wvl, *woh, *wol;
    cudaGetSymbolAddress((void**)&q,    g_q);
    cudaGetSymbolAddress((void**)&k,    g_k);
    cudaGetSymbolAddress((void**)&v,    g_v);
    cudaGetSymbolAddress((void**)&attn, g_attn);
    cudaGetSymbolAddress((void**)&Sq,   g_Sq);
    cudaGetSymbolAddress((void**)&Sk,   g_Sk);
    cudaGetSymbolAddress((void**)&idx,  g_idx);
    cudaGetSymbolAddress((void**)&xh,   g_xh);
    cudaGetSymbolAddress((void**)&xl,   g_xl);
    cudaGetSymbolAddress((void**)&wqh,  g_wqTh);
    cudaGetSymbolAddress((void**)&wql,  g_wqTl);
    cudaGetSymbolAddress((void**)&wkh,  g_wkTh);
    cudaGetSymbolAddress((void**)&wkl,  g_wkTl);
    cudaGetSymbolAddress((void**)&wvh,  g_wvTh);
    cudaGetSymbolAddress((void**)&wvl,  g_wvTl);
    cudaGetSymbolAddress((void**)&woh,  g_woTh);
    cudaGetSymbolAddress((void**)&wol,  g_woTl);

    const int attn_smem = (64 * QS * 2 + 64 * SS) * (int)sizeof(float);
    cudaFuncSetAttribute(attn_kernel, cudaFuncAttributeMaxDynamicSharedMemorySize, attn_smem);
    cudaFuncSetAttribute(gemm_split, cudaFuncAttributeMaxDynamicSharedMemorySize, GEMM_SMEM);

    init_invf<<<1, 64>>>();

    // split activations, transpose+split weights
    split_f32<<<(S_LEN * HID / 4 + 255) / 256, 256>>>(hs, xh, xl, S_LEN * HID / 4);
    transpose_split<<<dim3(2048 / 32, 2048 / 32), dim3(32, 8)>>>(Wq, wqh, wql, 2048, 2048);
    transpose_split<<<dim3(512 / 32,  2048 / 32), dim3(32, 8)>>>(Wk, wkh, wkl, 2048, 512);
    transpose_split<<<dim3(512 / 32,  2048 / 32), dim3(32, 8)>>>(Wv, wvh, wvl, 2048, 512);
    transpose_split<<<dim3(2048 / 32, 2048 / 32), dim3(32, 8)>>>(Wo, woh, wol, 2048, 2048);

    // projections (split-bf16 HMMA)
    gemm_split<<<dim3(2048 / 128, S_LEN / 128), 256, GEMM_SMEM>>>(xh, xl, wqh, wql, q, S_LEN, 2048, HID);
    gemm_split<<<dim3(512 / 128,  S_LEN / 128), 256, GEMM_SMEM>>>(xh, xl, wkh, wkl, k, S_LEN, 512, HID);
    gemm_split<<<dim3(512 / 128,  S_LEN / 128), 256, GEMM_SMEM>>>(xh, xl, wvh, wvl, v, S_LEN, 512, HID);

    // RoPE
    rope_kernel<<<(S_LEN * NH * 64 + 255) / 256, 256>>>(q, pos, NH);
    rope_kernel<<<(S_LEN * NKV * 64 + 255) / 256, 256>>>(k, pos, NKV);

    // sketches + top-k
    sketch_kernel<<<dim3(NBLK, NH),  DH>>>(q, Hs, Sq, NH, NH * DH);
    sketch_kernel<<<dim3(NBLK, NKV), DH>>>(k, Hs, Sk, NKV, NKV * DH);
    topk_kernel<<<NH, NBLK>>>(Sq, Sk, idx);

    // sparse attention
    attn_kernel<<<dim3(NBLK, NH), 256, attn_smem>>>(q, k, v, idx, attn);

    // output projection
    split_f32<<<(S_LEN * HID / 4 + 255) / 256, 256>>>(attn, xh, xl, S_LEN * HID / 4);
    gemm_split<<<dim3(2048 / 128, S_LEN / 128), 256, GEMM_SMEM>>>(xh, xl, woh, wol, out, S_LEN, 2048, HID);
}

// round 16
// speedup vs baseline: 2.6835x; 1.2482x over previous
#include <cuda_runtime.h>
#include <cuda_bf16.h>
#include <math.h>
#include <stdint.h>
#include <cstdint>

// ---------------------------------------------------------------------------
// SketchWalkLlamaAttention  (B=1, S=4096, HID=2048, NH=16, NKV=4, D=128,
//                            BLK=64, M=32, K_TOP=8, nblk=64)
// R14: attention QK^T and P.V moved to split-bf16 HMMA (mma.sync m16n8k16):
//   q/k/v pre-split to bf16 hi/lo; QK uses non-trans ldmatrix (K as [N][K]),
//   PV uses ldmatrix.x4.trans on V's natural [kc][d] layout. Scores fp32 in
//   smem; softmax unchanged; P split per k-block into the dead Q buffers.
// ---------------------------------------------------------------------------

#define S_LEN 4096
#define HID   2048
#define NH    16
#define NKV   4
#define DH    128
#define BLK   64
#define NBLK  64
#define MSK   32
#define KTOP  8
#define NEGV  (-1e9f)

// scratch (device globals: no allocation allowed)
__device__ float g_q[S_LEN * NH * DH];
__device__ float g_k[S_LEN * NKV * DH];
__device__ float g_v[S_LEN * NKV * DH];
__device__ float g_attn[S_LEN * NH * DH];
__device__ float g_Sq[NH * NBLK * MSK];
__device__ float g_Sk[NKV * NBLK * MSK];
__device__ int   g_idx[NH * NBLK * KTOP];
__device__ float g_invf[64];

// bf16 split-precision operand buffers
__device__ __nv_bfloat16 g_xh[S_LEN * HID];
__device__ __nv_bfloat16 g_xl[S_LEN * HID];
__device__ __nv_bfloat16 g_wqTh[2048 * 2048], g_wqTl[2048 * 2048];
__device__ __nv_bfloat16 g_wkTh[512 * 2048],  g_wkTl[512 * 2048];
__device__ __nv_bfloat16 g_wvTh[512 * 2048],  g_wvTl[512 * 2048];
__device__ __nv_bfloat16 g_woTh[2048 * 2048], g_woTl[2048 * 2048];
// attention operand splits (q/k post-rope, v raw)
__device__ __nv_bfloat16 g_qh[S_LEN * NH * DH],  g_ql[S_LEN * NH * DH];
__device__ __nv_bfloat16 g_kh[S_LEN * NKV * DH], g_kl[S_LEN * NKV * DH];
__device__ __nv_bfloat16 g_vh[S_LEN * NKV * DH], g_vl[S_LEN * NKV * DH];

__device__ __forceinline__ uint32_t smem_u32(const void* p) {
    uint32_t a;
    asm("{ .reg .u64 t; cvta.to.shared.u64 t, %1; cvt.u32.u64 %0, t; }" : "=r"(a) : "l"(p));
    return a;
}

#define MMA16816(c, a, b) \
    asm volatile("mma.sync.aligned.m16n8k16.row.col.f32.bf16.bf16.f32 " \
                 "{%0,%1,%2,%3}, {%4,%5,%6,%7}, {%8,%9}, {%0,%1,%2,%3};" \
                 : "+f"((c)[0]), "+f"((c)[1]), "+f"((c)[2]), "+f"((c)[3]) \
                 : "r"((a)[0]), "r"((a)[1]), "r"((a)[2]), "r"((a)[3]), \
                   "r"((b)[0]), "r"((b)[1]))

__device__ __forceinline__ void ldsm_x4(uint32_t r[4], uint32_t addr) {
    asm volatile("ldmatrix.sync.aligned.m8n8.x4.shared.b16 {%0,%1,%2,%3}, [%4];"
                 : "=r"(r[0]), "=r"(r[1]), "=r"(r[2]), "=r"(r[3]) : "r"(addr));
}
__device__ __forceinline__ void ldsm_x4_t(uint32_t r[4], uint32_t addr) {
    asm volatile("ldmatrix.sync.aligned.m8n8.x4.trans.shared.b16 {%0,%1,%2,%3}, [%4];"
                 : "=r"(r[0]), "=r"(r[1]), "=r"(r[2]), "=r"(r[3]) : "r"(addr));
}
#define CPASYNC16(d, s) \
    asm volatile("cp.async.cg.shared.global [%0], [%1], 16;" :: "r"(d), "l"(s))

// ---------------------------------------------------------------------------
// fp32 -> (hi, lo) bf16 split, vectorized
// ---------------------------------------------------------------------------
__global__ void split_f32(const float* __restrict__ A, __nv_bfloat16* __restrict__ H,
                          __nv_bfloat16* __restrict__ L, int n4)
{
    int i = blockIdx.x * blockDim.x + threadIdx.x;
    if (i >= n4) return;
    float4 v = ((const float4*)A)[i];
    float f[4] = {v.x, v.y, v.z, v.w};
    __nv_bfloat16 h[4], l[4];
#pragma unroll
    for (int j = 0; j < 4; j++) {
        h[j] = __float2bfloat16(f[j]);
        l[j] = __float2bfloat16(f[j] - __bfloat162float(h[j]));
    }
    ((__nv_bfloat162*)H)[2 * i]     = __nv_bfloat162(h[0], h[1]);
    ((__nv_bfloat162*)H)[2 * i + 1] = __nv_bfloat162(h[2], h[3]);
    ((__nv_bfloat162*)L)[2 * i]     = __nv_bfloat162(l[0], l[1]);
    ((__nv_bfloat162*)L)[2 * i + 1] = __nv_bfloat162(l[2], l[3]);
}

// ---------------------------------------------------------------------------
// W [K,N] fp32 row-major -> T [N,K] bf16 hi/lo
// ---------------------------------------------------------------------------
__global__ void transpose_split(const float* __restrict__ W, __nv_bfloat16* __restrict__ Th,
                                __nv_bfloat16* __restrict__ Tl, int K, int N)
{
    __shared__ float tile[32][33];
    int n0 = blockIdx.x * 32, k0 = blockIdx.y * 32;
    int tx = threadIdx.x, ty = threadIdx.y; // 32 x 8
#pragma unroll
    for (int i = 0; i < 32; i += 8)
        tile[ty + i][tx] = W[(size_t)(k0 + ty + i) * N + n0 + tx];
    __syncthreads();
#pragma unroll
    for (int i = 0; i < 32; i += 8) {
        float v = tile[tx][ty + i];
        __nv_bfloat16 h = __float2bfloat16(v);
        float lo = v - __bfloat162float(h);
        size_t o = (size_t)(n0 + ty + i) * K + k0 + tx;
        Th[o] = h;
        Tl[o] = __float2bfloat16(lo);
    }
}

// ---------------------------------------------------------------------------
// Split-bf16 HMMA GEMM (unchanged from R9/R14, passing)
// ---------------------------------------------------------------------------
#define BK 32
#define ASTRIDE_B 80
#define TILE_BYTES (128 * ASTRIDE_B)
#define BUF_BYTES  (4 * TILE_BYTES)
#define GEMM_SMEM  (2 * BUF_BYTES)

__device__ __forceinline__ void issue_chunk(
    const __nv_bfloat16* gAh, const __nv_bfloat16* gAl,
    const __nv_bfloat16* gBh, const __nv_bfloat16* gBl,
    int K, int k0, uint32_t sdst, int tid)
{
#pragma unroll
    for (int it = 0; it < 2; it++) {
        int idx = tid + it * 256;
        int r = idx >> 2, cc = idx & 3;
        size_t off = (size_t)r * K + k0 + cc * 8;
        uint32_t d0 = sdst + r * ASTRIDE_B + cc * 16;
        CPASYNC16(d0, gAh + off);
        CPASYNC16(d0 + TILE_BYTES, gAl + off);
        CPASYNC16(d0 + 2 * TILE_BYTES, gBh + off);
        CPASYNC16(d0 + 3 * TILE_BYTES, gBl + off);
    }
    asm volatile("cp.async.commit_group;" ::: "memory");
}

__global__ __launch_bounds__(256)
void gemm_split(const __nv_bfloat16* __restrict__ Ah, const __nv_bfloat16* __restrict__ Al,
                const __nv_bfloat16* __restrict__ Bh, const __nv_bfloat16* __restrict__ Bl,
                float* __restrict__ C, int M, int N, int K)
{
    extern __shared__ char dsm[];
    const int tid = threadIdx.x, lane = tid & 31, wid = tid >> 5;
    const int warp_m = wid & 1, warp_n = wid >> 1;
    const int g = lane >> 2, tg = lane & 3;
    const int row0 = blockIdx.y * 128, col0 = blockIdx.x * 128;

    const int arow  = lane & 15;
    const int acol  = (lane >> 4) * 16;
    const int brow  = ((lane >> 4) << 3) | (lane & 7);
    const int bcol  = ((lane >> 3) & 1) * 16;

    const __nv_bfloat16* gAh = Ah + (size_t)row0 * K;
    const __nv_bfloat16* gAl = Al + (size_t)row0 * K;
    const __nv_bfloat16* gBh = Bh + (size_t)col0 * K;
    const __nv_bfloat16* gBl = Bl + (size_t)col0 * K;
    const uint32_t sbase = smem_u32(dsm);

    float acc[4][4][4];
#pragma unroll
    for (int mt = 0; mt < 4; mt++)
#pragma unroll
        for (int nt = 0; nt < 4; nt++)
#pragma unroll
            for (int e = 0; e < 4; e++) acc[mt][nt][e] = 0.f;

    const int nchunk = K / BK;
    issue_chunk(gAh, gAl, gBh, gBl, K, 0, sbase, tid);

    for (int c = 0; c < nchunk; c++) {
        if (c + 1 < nchunk) {
            issue_chunk(gAh, gAl, gBh, gBl, K, (c + 1) * BK,
                        sbase + ((c + 1) & 1) * BUF_BYTES, tid);
            asm volatile("cp.async.wait_group 1;" ::: "memory");
        } else {
            asm volatile("cp.async.wait_group 0;" ::: "memory");
        }
        __syncthreads();

        const uint32_t bufu = sbase + (c & 1) * BUF_BYTES;
        const uint32_t tAh = bufu;
        const uint32_t tAl = bufu + TILE_BYTES;
        const uint32_t tBh = bufu + 2 * TILE_BYTES;
        const uint32_t tBl = bufu + 3 * TILE_BYTES;

#pragma unroll
        for (int ks = 0; ks < 2; ks++) {
            const int kb = ks * 32;
            uint32_t a[4][4], bh[4][2], bl[4][2];
#pragma unroll
            for (int mt = 0; mt < 4; mt++)
                ldsm_x4(a[mt], tAh + (warp_m * 64 + mt * 16 + arow) * ASTRIDE_B + kb + acol);
#pragma unroll
            for (int p = 0; p < 2; p++) {
                uint32_t t[4];
                ldsm_x4(t, tBh + (warp_n * 32 + p * 16 + brow) * ASTRIDE_B + kb + bcol);
                bh[2 * p][0] = t[0]; bh[2 * p][1] = t[1];
                bh[2 * p + 1][0] = t[2]; bh[2 * p + 1][1] = t[3];
            }
#pragma unroll
            for (int p = 0; p < 2; p++) {
                uint32_t t[4];
                ldsm_x4(t, tBl + (warp_n * 32 + p * 16 + brow) * ASTRIDE_B + kb + bcol);
                bl[2 * p][0] = t[0]; bl[2 * p][1] = t[1];
                bl[2 * p + 1][0] = t[2]; bl[2 * p + 1][1] = t[3];
            }
#pragma unroll
            for (int mt = 0; mt < 4; mt++)
#pragma unroll
                for (int nt = 0; nt < 4; nt++) MMA16816(acc[mt][nt], a[mt], bh[nt]);
#pragma unroll
            for (int mt = 0; mt < 4; mt++)
#pragma unroll
                for (int nt = 0; nt < 4; nt++) MMA16816(acc[mt][nt], a[mt], bl[nt]);
#pragma unroll
            for (int mt = 0; mt < 4; mt++)
                ldsm_x4(a[mt], tAl + (warp_m * 64 + mt * 16 + arow) * ASTRIDE_B + kb + acol);
#pragma unroll
            for (int mt = 0; mt < 4; mt++)
#pragma unroll
                for (int nt = 0; nt < 4; nt++) MMA16816(acc[mt][nt], a[mt], bh[nt]);
        }
        __syncthreads();
    }

#pragma unroll
    for (int mt = 0; mt < 4; mt++) {
        int r = row0 + warp_m * 64 + mt * 16 + g;
#pragma unroll
        for (int nt = 0; nt < 4; nt++) {
            int cc = col0 + warp_n * 32 + nt * 8 + tg * 2;
            *(float2*)&C[(size_t)r * N + cc]       = make_float2(acc[mt][nt][0], acc[mt][nt][1]);
            *(float2*)&C[(size_t)(r + 8) * N + cc] = make_float2(acc[mt][nt][2], acc[mt][nt][3]);
        }
    }
}

// ---------------------------------------------------------------------------
__global__ void init_invf()
{
    int i = threadIdx.x;
    if (i < 64) g_invf[i] = (float)exp(-(double)i * 0.14391156831212787); // ln(1e4)/64
}

__global__ void rope_kernel(float* __restrict__ x, const int* __restrict__ pos, int H)
{
    int i = blockIdx.x * blockDim.x + threadIdx.x;
    int total = S_LEN * H * 64;
    if (i >= total) return;
    int half = i & 63;
    int sh = i >> 6;
    int s = sh / H;
    float p = (float)pos[s];
    float ang = p * g_invf[half];
    float sn, cs;
    sincosf(ang, &sn, &cs);
    float* base = x + (size_t)sh * DH;
    float x1 = base[half];
    float x2 = base[half + 64];
    base[half]      = x1 * cs - x2 * sn;
    base[half + 64] = x2 * cs + x1 * sn;
}

__global__ void sketch_kernel(const float* __restrict__ x, const float* __restrict__ Hs,
                              float* __restrict__ Sout, int heads, int stride)
{
    int blk = blockIdx.x, h = blockIdx.y;
    int d = threadIdx.x;
    __shared__ float mean[DH];
    float acc = 0.f;
    const float* base = x + (size_t)(blk * BLK) * stride + h * DH + d;
    for (int r = 0; r < BLK; r++) acc += base[(size_t)r * stride];
    mean[d] = acc * (1.f / 64.f);
    __syncthreads();
    if (d < MSK) {
        float s = 0.f;
#pragma unroll 16
        for (int dd = 0; dd < DH; dd++) s = fmaf(mean[dd], Hs[dd * MSK + d], s);
        Sout[((size_t)h * NBLK + blk) * MSK + d] = s;
    }
}

__global__ void topk_kernel(const float* __restrict__ Sq, const float* __restrict__ Sk,
                            int* __restrict__ idx_out)
{
    int h = blockIdx.x;
    int qb = threadIdx.x;
    int kvh = h >> 2;
    const float* sq = Sq + ((size_t)h * NBLK + qb) * MSK;
    float vals[NBLK];
    for (int j = 0; j < NBLK; j++) {
        if (j > qb)       vals[j] = NEGV;
        else if (j == qb) vals[j] = 1e9f;
        else {
            const float* sk = Sk + ((size_t)kvh * NBLK + j) * MSK;
            float s = 0.f;
#pragma unroll
            for (int m = 0; m < MSK; m++) s = fmaf(sq[m], sk[m], s);
            vals[j] = s;
        }
    }
    for (int t = 0; t < KTOP; t++) {
        float best = -3e9f; int bi = 0;
        for (int j = 0; j < NBLK; j++)
            if (vals[j] > best) { best = vals[j]; bi = j; }
        idx_out[((size_t)h * NBLK + qb) * KTOP + t] = bi;
        vals[bi] = -4e9f;
    }
}

// ---------------------------------------------------------------------------
// Sparse block attention on split-bf16 HMMA. grid (NBLK, NH), 256 thr, 8 warps.
// smem: Sc 64x520 fp32 (133120 B) + 4 bf16 tiles 64x136 halves (17408 B each):
//   tile0/1 = Qh/Ql (reused as Ph/Pl), tile2/3 = Kh/Kl (reused as Vh/Vl).
// Row stride 272 B == 4 banks -> every ldmatrix phase conflict-free.
// ---------------------------------------------------------------------------
#define SS 520
#define TSTR 136                        // halves per tile row
#define ATILE_B (64 * TSTR * 2)         // 17408
#define SC_BYTES (64 * SS * 4)          // 133120
#define ATTN_SMEM (SC_BYTES + 4 * ATILE_B)  // 202752

__global__ __launch_bounds__(256, 1)
void attn_kernel(const __nv_bfloat16* __restrict__ qh, const __nv_bfloat16* __restrict__ ql,
                 const __nv_bfloat16* __restrict__ kh, const __nv_bfloat16* __restrict__ kl,
                 const __nv_bfloat16* __restrict__ vh, const __nv_bfloat16* __restrict__ vl,
                 const int* __restrict__ idxs, float* __restrict__ out)
{
    extern __shared__ char smraw[];
    float* Sc = (float*)smraw;
    char* t0 = smraw + SC_BYTES;            // Qh / Ph
    char* t1 = t0 + ATILE_B;                // Ql / Pl
    char* t2 = t1 + ATILE_B;                // Kh / Vh
    char* t3 = t2 + ATILE_B;                // Kl / Vl
    __shared__ int sel[KTOP];

    const uint32_t u0 = smem_u32(t0), u1 = smem_u32(t1), u2 = smem_u32(t2), u3 = smem_u32(t3);

    const int qb = blockIdx.x, h = blockIdx.y;
    const int kvh = h >> 2;
    const int tid = threadIdx.x, lane = tid & 31, wid = tid >> 5;
    const int g = lane >> 2, tg = lane & 3;
    const int mt = wid >> 1;                // m16 tile 0..3
    const int nq = wid & 1;                 // n-half within 64-col block (QK)
    const int dh = wid & 1;                 // d-half (PV)

    // ldmatrix lane addressing
    const int arow = lane & 15, acol = (lane >> 4) * 16;               // A, non-trans
    const int brow = ((lane >> 4) << 3) | (lane & 7);                  // B, non-trans
    const int bcol = ((lane >> 3) & 1) * 16;
    const int trow = (lane & 7) + (((lane >> 3) & 1) << 3);            // B, trans
    const int tcol = ((lane >> 4) & 1) * 8;                            // halves

    // ---- load Q tiles (hi/lo), 1024 16B slots each ----
    for (int idx = tid; idx < 1024; idx += 256) {
        int r = idx >> 4, cc = idx & 15;
        size_t off = (size_t)(qb * BLK + r) * (NH * DH) + h * DH + cc * 8;
        uint32_t d = r * (TSTR * 2) + cc * 16;
        CPASYNC16(u0 + d, qh + off);
        CPASYNC16(u1 + d, ql + off);
    }
    asm volatile("cp.async.commit_group;" ::: "memory");
    if (tid < KTOP) sel[tid] = idxs[((size_t)h * NBLK + qb) * KTOP + tid];
    asm volatile("cp.async.wait_group 0;" ::: "memory");
    __syncthreads();

    const float scale = 0.08838834764831845f; // 1/sqrt(128)

    // ================= QK^T =================
    for (int kb = 0; kb < KTOP; kb++) {
        int jb = sel[kb];
        for (int idx = tid; idx < 1024; idx += 256) {
            int r = idx >> 4, cc = idx & 15;
            size_t off = (size_t)(jb * BLK + r) * (NKV * DH) + kvh * DH + cc * 8;
            uint32_t d = r * (TSTR * 2) + cc * 16;
            CPASYNC16(u2 + d, kh + off);
            CPASYNC16(u3 + d, kl + off);
        }
        asm volatile("cp.async.commit_group;" ::: "memory");
        asm volatile("cp.async.wait_group 0;" ::: "memory");
        __syncthreads();

        float facc[4][4];
#pragma unroll
        for (int nt = 0; nt < 4; nt++)
#pragma unroll
            for (int e = 0; e < 4; e++) facc[nt][e] = 0.f;

#pragma unroll
        for (int ks = 0; ks < 8; ks++) {            // d = 128 -> 8 k16 steps
            const int kbyte = ks * 32;
            uint32_t a[4], bh2[4][2], bl2[4][2];
            ldsm_x4(a, u0 + (mt * 16 + arow) * (TSTR * 2) + kbyte + acol);
#pragma unroll
            for (int p = 0; p < 2; p++) {
                uint32_t t[4];
                ldsm_x4(t, u2 + (nq * 32 + p * 16 + brow) * (TSTR * 2) + kbyte + bcol);
                bh2[2 * p][0] = t[0]; bh2[2 * p][1] = t[1];
                bh2[2 * p + 1][0] = t[2]; bh2[2 * p + 1][1] = t[3];
                ldsm_x4(t, u3 + (nq * 32 + p * 16 + brow) * (TSTR * 2) + kbyte + bcol);
                bl2[2 * p][0] = t[0]; bl2[2 * p][1] = t[1];
                bl2[2 * p + 1][0] = t[2]; bl2[2 * p + 1][1] = t[3];
            }
#pragma unroll
            for (int nt = 0; nt < 4; nt++) MMA16816(facc[nt], a, bh2[nt]);
#pragma unroll
            for (int nt = 0; nt < 4; nt++) MMA16816(facc[nt], a, bl2[nt]);
            ldsm_x4(a, u1 + (mt * 16 + arow) * (TSTR * 2) + kbyte + acol);
#pragma unroll
            for (int nt = 0; nt < 4; nt++) MMA16816(facc[nt], a, bh2[nt]);
        }

        // write scores with mask+scale
#pragma unroll
        for (int nt = 0; nt < 4; nt++) {
            int col = nq * 32 + nt * 8 + tg * 2;
            int kpos0 = jb * BLK + col;
#pragma unroll
            for (int half = 0; half < 2; half++) {
                int qr = mt * 16 + g + half * 8;
                int qpos = qb * BLK + qr;
                float* dst = &Sc[qr * SS + kb * BLK + col];
                dst[0] = (kpos0     <= qpos) ? facc[nt][2 * half]     * scale : NEGV;
                dst[1] = (kpos0 + 1 <= qpos) ? facc[nt][2 * half + 1] * scale : NEGV;
            }
        }
        __syncthreads();
    }

    // ================= softmax (4 threads/row) =================
    {
        int row = tid >> 2, sl = tid & 3;
        float* srow = Sc + row * SS;
        float mx = -3e30f;
        for (int c = sl; c < KTOP * BLK; c += 4) mx = fmaxf(mx, srow[c]);
        mx = fmaxf(mx, __shfl_xor_sync(0xffffffffu, mx, 1));
        mx = fmaxf(mx, __shfl_xor_sync(0xffffffffu, mx, 2));
        float sum = 0.f;
        for (int c = sl; c < KTOP * BLK; c += 4) {
            float e = expf(srow[c] - mx);
            srow[c] = e;
            sum += e;
        }
        sum += __shfl_xor_sync(0xffffffffu, sum, 1);
        sum += __shfl_xor_sync(0xffffffffu, sum, 2);
        float invs = 1.f / sum;
        for (int c = sl; c < KTOP * BLK; c += 4) srow[c] *= invs;
    }
    __syncthreads();

    // ================= P.V =================
    float oacc[8][4];
#pragma unroll
    for (int nt = 0; nt < 8; nt++)
#pragma unroll
        for (int e = 0; e < 4; e++) oacc[nt][e] = 0.f;

    for (int kb = 0; kb < KTOP; kb++) {
        int jb = sel[kb];
        // V tiles (async) — overlapped with P split below
        for (int idx = tid; idx < 1024; idx += 256) {
            int r = idx >> 4, cc = idx & 15;
            size_t off = (size_t)(jb * BLK + r) * (NKV * DH) + kvh * DH + cc * 8;
            uint32_t d = r * (TSTR * 2) + cc * 16;
            CPASYNC16(u2 + d, vh + off);
            CPASYNC16(u3 + d, vl + off);
        }
        asm volatile("cp.async.commit_group;" ::: "memory");
        // split P block into Ph/Pl (t0/t1)
        for (int idx = tid; idx < 4096; idx += 256) {
            int r = idx >> 6, cc = idx & 63;
            float p = Sc[r * SS + kb * BLK + cc];
            __nv_bfloat16 ph = __float2bfloat16(p);
            __nv_bfloat16 pl = __float2bfloat16(p - __bfloat162float(ph));
            ((__nv_bfloat16*)t0)[r * TSTR + cc] = ph;
            ((__nv_bfloat16*)t1)[r * TSTR + cc] = pl;
        }
        asm volatile("cp.async.wait_group 0;" ::: "memory");
        __syncthreads();

#pragma unroll
        for (int ks = 0; ks < 4; ks++) {            // kc = 64 -> 4 k16 steps
            const int kbyte = ks * 32;
            uint32_t a[4], bh2[8][2], bl2[8][2];
            ldsm_x4(a, u0 + (mt * 16 + arow) * (TSTR * 2) + kbyte + acol);
#pragma unroll
            for (int p = 0; p < 4; p++) {           // 8 n8 tiles over 64 d cols
                uint32_t t[4];
                uint32_t baddr = (ks * 16 + trow) * (TSTR * 2) + (dh * 64 + p * 16 + tcol) * 2;
                ldsm_x4_t(t, u2 + baddr);
                bh2[2 * p][0] = t[0]; bh2[2 * p][1] = t[1];
                bh2[2 * p + 1][0] = t[2]; bh2[2 * p + 1][1] = t[3];
                ldsm_x4_t(t, u3 + baddr);
                bl2[2 * p][0] = t[0]; bl2[2 * p][1] = t[1];
                bl2[2 * p + 1][0] = t[2]; bl2[2 * p + 1][1] = t[3];
            }
#pragma unroll
            for (int nt = 0; nt < 8; nt++) MMA16816(oacc[nt], a, bh2[nt]);
#pragma unroll
            for (int nt = 0; nt < 8; nt++) MMA16816(oacc[nt], a, bl2[nt]);
            ldsm_x4(a, u1 + (mt * 16 + arow) * (TSTR * 2) + kbyte + acol);
#pragma unroll
            for (int nt = 0; nt < 8; nt++) MMA16816(oacc[nt], a, bh2[nt]);
        }
        __syncthreads();
    }

    // write output
#pragma unroll
    for (int nt = 0; nt < 8; nt++) {
        int col = h * DH + dh * 64 + nt * 8 + tg * 2;
#pragma unroll
        for (int half = 0; half < 2; half++) {
            int qr = mt * 16 + g + half * 8;
            *(float2*)&out[(size_t)(qb * BLK + qr) * (NH * DH) + col] =
                make_float2(oacc[nt][2 * half], oacc[nt][2 * half + 1]);
        }
    }
}

// ---------------------------------------------------------------------------
extern "C" void kernel_launch(void* const* d_in, const int* in_sizes, int n_in,
                              void* d_out, int out_size)
{
    const float* hs  = (const float*)d_in[0];
    const int*   pos = (const int*)d_in[1];
    const float* Wq  = (const float*)d_in[2];
    const float* Wk  = (const float*)d_in[3];
    const float* Wv  = (const float*)d_in[4];
    const float* Wo  = (const float*)d_in[5];
    const float* Hs  = (const float*)d_in[6];
    float* out = (float*)d_out;

    float *q, *k, *v, *attn, *Sq, *Sk;
    int* idx;
    __nv_bfloat16 *xh, *xl, *wqh, *wql, *wkh, *wkl, *wvh, *wvl, *woh, *wol;
    __nv_bfloat16 *qh, *ql, *kh, *kl, *vh, *vl;
    cudaGetSymbolAddress((void**)&q,    g_q);
    cudaGetSymbolAddress((void**)&k,    g_k);
    cudaGetSymbolAddress((void**)&v,    g_v);
    cudaGetSymbolAddress((void**)&attn, g_attn);
    cudaGetSymbolAddress((void**)&Sq,   g_Sq);
    cudaGetSymbolAddress((void**)&Sk,   g_Sk);
    cudaGetSymbolAddress((void**)&idx,  g_idx);
    cudaGetSymbolAddress((void**)&xh,   g_xh);
    cudaGetSymbolAddress((void**)&xl,   g_xl);
    cudaGetSymbolAddress((void**)&wqh,  g_wqTh);
    cudaGetSymbolAddress((void**)&wql,  g_wqTl);
    cudaGetSymbolAddress((void**)&wkh,  g_wkTh);
    cudaGetSymbolAddress((void**)&wkl,  g_wkTl);
    cudaGetSymbolAddress((void**)&wvh,  g_wvTh);
    cudaGetSymbolAddress((void**)&wvl,  g_wvTl);
    cudaGetSymbolAddress((void**)&woh,  g_woTh);
    cudaGetSymbolAddress((void**)&wol,  g_woTl);
    cudaGetSymbolAddress((void**)&qh,   g_qh);
    cudaGetSymbolAddress((void**)&ql,   g_ql);
    cudaGetSymbolAddress((void**)&kh,   g_kh);
    cudaGetSymbolAddress((void**)&kl,   g_kl);
    cudaGetSymbolAddress((void**)&vh,   g_vh);
    cudaGetSymbolAddress((void**)&vl,   g_vl);

    cudaFuncSetAttribute(attn_kernel, cudaFuncAttributeMaxDynamicSharedMemorySize, ATTN_SMEM);
    cudaFuncSetAttribute(gemm_split, cudaFuncAttributeMaxDynamicSharedMemorySize, GEMM_SMEM);

    init_invf<<<1, 64>>>();

    // split activations, transpose+split weights
    split_f32<<<(S_LEN * HID / 4 + 255) / 256, 256>>>(hs, xh, xl, S_LEN * HID / 4);
    transpose_split<<<dim3(2048 / 32, 2048 / 32), dim3(32, 8)>>>(Wq, wqh, wql, 2048, 2048);
    transpose_split<<<dim3(512 / 32,  2048 / 32), dim3(32, 8)>>>(Wk, wkh, wkl, 2048, 512);
    transpose_split<<<dim3(512 / 32,  2048 / 32), dim3(32, 8)>>>(Wv, wvh, wvl, 2048, 512);
    transpose_split<<<dim3(2048 / 32, 2048 / 32), dim3(32, 8)>>>(Wo, woh, wol, 2048, 2048);

    // projections (split-bf16 HMMA)
    gemm_split<<<dim3(2048 / 128, S_LEN / 128), 256, GEMM_SMEM>>>(xh, xl, wqh, wql, q, S_LEN, 2048, HID);
    gemm_split<<<dim3(512 / 128,  S_LEN / 128), 256, GEMM_SMEM>>>(xh, xl, wkh, wkl, k, S_LEN, 512, HID);
    gemm_split<<<dim3(512 / 128,  S_LEN / 128), 256, GEMM_SMEM>>>(xh, xl, wvh, wvl, v, S_LEN, 512, HID);

    // RoPE
    rope_kernel<<<(S_LEN * NH * 64 + 255) / 256, 256>>>(q, pos, NH);
    rope_kernel<<<(S_LEN * NKV * 64 + 255) / 256, 256>>>(k, pos, NKV);

    // split q/k (post-rope) and v for HMMA attention
    split_f32<<<(S_LEN * NH * DH / 4 + 255) / 256, 256>>>(q, qh, ql, S_LEN * NH * DH / 4);
    split_f32<<<(S_LEN * NKV * DH / 4 + 255) / 256, 256>>>(k, kh, kl, S_LEN * NKV * DH / 4);
    split_f32<<<(S_LEN * NKV * DH / 4 + 255) / 256, 256>>>(v, vh, vl, S_LEN * NKV * DH / 4);

    // sketches + top-k
    sketch_kernel<<<dim3(NBLK, NH),  DH>>>(q, Hs, Sq, NH, NH * DH);
    sketch_kernel<<<dim3(NBLK, NKV), DH>>>(k, Hs, Sk, NKV, NKV * DH);
    topk_kernel<<<NH, NBLK>>>(Sq, Sk, idx);

    // sparse attention (split-bf16 HMMA)
    attn_kernel<<<dim3(NBLK, NH), 256, ATTN_SMEM>>>(qh, ql, kh, kl, vh, vl, idx, attn);

    // output projection
    split_f32<<<(S_LEN * HID / 4 + 255) / 256, 256>>>(attn, xh, xl, S_LEN * HID / 4);
    gemm_split<<<dim3(2048 / 128, S_LEN / 128), 256, GEMM_SMEM>>>(xh, xl, woh, wol, out, S_LEN, 2048, HID);
}